// round 9
// baseline (speedup 1.0000x reference)
#include <cuda_runtime.h>
#include <cuda_fp16.h>
#include <cstdint>

#define DIN 128
#define DOUT 128
#define NEG_SLOPE 0.2f
#define MAX_N 50048
#define MAX_EN 860000   // E + N with slack

// ---------------- scratch (no allocations allowed) ----------------
__device__ __half   g_xw_h[(size_t)MAX_N * DOUT]; // x @ W (fp16, for gather)
__device__ float    g_asrc[MAX_N];
__device__ float    g_adst[MAX_N];
__device__ int      g_deg[MAX_N];                 // in-degree histogram
__device__ int      g_start[MAX_N + 1];           // CSR row offsets (by dst)
__device__ int      g_cursor[MAX_N];              // scatter cursors
__device__ int      g_csr_src[MAX_EN];            // src node per CSR slot
__device__ float    g_ev[MAX_EN];                 // leaky-relu logit per CSR slot
__device__ int      g_is64;

// ---------------- kernels ----------------

// Zero histogram + detect int64 vs int32 edge_index (block 0 thread 0).
__global__ void k_zero(const long long* ei, int n) {
    int i = blockIdx.x * blockDim.x + threadIdx.x;
    if (i < n) g_deg[i] = 0;
    if (i == 0) {
        bool ok = true;
#pragma unroll
        for (int t = 0; t < 8; t++) {
            long long v = ei[t];
            if (v < 0 || v >= (long long)n) ok = false;
        }
        g_is64 = ok ? 1 : 0;
    }
}

// Histogram of destinations (incl. self loops appended at the end).
__global__ void k_hist(const void* ei, int E, int n) {
    int i = blockIdx.x * blockDim.x + threadIdx.x;
    if (i >= E + n) return;
    int d;
    if (i >= E) d = i - E;
    else if (g_is64) d = (int)((const long long*)ei)[i + E];
    else             d = ((const int*)ei)[i + E];
    atomicAdd(&g_deg[d], 1);
}

// ---------------- GEMM (measured ~88% of fp32 SIMT roofline) -----------------
// xw = x @ W. 64 rows x 128 cols per block, 256 threads, BK=32.
// Fused epilogue: attention row-dots (warp shfl reduce) + fp16 store of xw.
__global__ __launch_bounds__(256) void k_gemm(const float* __restrict__ x,
                                              const float* __restrict__ W,
                                              const float* __restrict__ att_src,
                                              const float* __restrict__ att_dst,
                                              int n) {
    __shared__ float As[64][32];
    __shared__ float Bs[32][128];
    const int tid = threadIdx.x;
    const int block_row = blockIdx.x * 64;
    const int ty = tid >> 5, tx = tid & 31;
    float acc[8][4] = {};

    for (int k0 = 0; k0 < DIN; k0 += 32) {
#pragma unroll
        for (int t = tid; t < 512; t += 256) {           // A: 64x32 = 512 float4
            int r = t >> 3, kq = t & 7;
            int row = block_row + r; if (row >= n) row = n - 1;
            *(float4*)&As[r][kq * 4] =
                *(const float4*)(x + (size_t)row * DIN + k0 + kq * 4);
        }
#pragma unroll
        for (int t = tid; t < 1024; t += 256) {          // B: 32x128 = 1024 float4
            int k = t >> 5, cq = t & 31;
            *(float4*)&Bs[k][cq * 4] =
                *(const float4*)(W + (size_t)(k0 + k) * DOUT + cq * 4);
        }
        __syncthreads();
#pragma unroll
        for (int k = 0; k < 32; k++) {
            float4 b = *(float4*)&Bs[k][tx * 4];
#pragma unroll
            for (int r = 0; r < 8; r++) {
                float a = As[ty * 8 + r][k];
                acc[r][0] += a * b.x;
                acc[r][1] += a * b.y;
                acc[r][2] += a * b.z;
                acc[r][3] += a * b.w;
            }
        }
        __syncthreads();
    }

    // fused epilogue: fp16 store + attention dots
    float4 sv = ((const float4*)att_src)[tx];
    float4 dv = ((const float4*)att_dst)[tx];
#pragma unroll
    for (int r = 0; r < 8; r++) {
        int row = block_row + ty * 8 + r;
        float ps = acc[r][0] * sv.x + acc[r][1] * sv.y + acc[r][2] * sv.z + acc[r][3] * sv.w;
        float pd = acc[r][0] * dv.x + acc[r][1] * dv.y + acc[r][2] * dv.z + acc[r][3] * dv.w;
#pragma unroll
        for (int o = 16; o; o >>= 1) {
            ps += __shfl_xor_sync(0xffffffffu, ps, o);
            pd += __shfl_xor_sync(0xffffffffu, pd, o);
        }
        if (row < n) {
            __half2 h0 = __floats2half2_rn(acc[r][0], acc[r][1]);
            __half2 h1 = __floats2half2_rn(acc[r][2], acc[r][3]);
            uint2 u; u.x = *(unsigned*)&h0; u.y = *(unsigned*)&h1;
            *(uint2*)(g_xw_h + (size_t)row * DOUT + tx * 4) = u;
            if (tx == 0) { g_asrc[row] = ps; g_adst[row] = pd; }
        }
    }
}

// Single-block exclusive scan of g_deg -> g_start/g_cursor (4 elems/thread).
__global__ __launch_bounds__(1024) void k_scan(int n) {
    __shared__ int warp_tot[32];
    __shared__ int s_carry;
    int tid = threadIdx.x, lane = tid & 31, wid = tid >> 5;
    if (tid == 0) s_carry = 0;
    __syncthreads();
    for (int base = 0; base < n; base += 4096) {
        int i0 = base + tid * 4;
        int4 v = make_int4(0, 0, 0, 0);
        if (i0 + 3 < n) v = *(const int4*)&g_deg[i0];
        else {
            if (i0 + 0 < n) v.x = g_deg[i0 + 0];
            if (i0 + 1 < n) v.y = g_deg[i0 + 1];
            if (i0 + 2 < n) v.z = g_deg[i0 + 2];
            if (i0 + 3 < n) v.w = g_deg[i0 + 3];
        }
        int s = v.x + v.y + v.z + v.w;
        int sc = s;
#pragma unroll
        for (int off = 1; off < 32; off <<= 1) {
            int t = __shfl_up_sync(0xffffffffu, sc, off);
            if (lane >= off) sc += t;
        }
        if (lane == 31) warp_tot[wid] = sc;
        __syncthreads();
        if (wid == 0) {
            int wv = warp_tot[lane];
            int wsc = wv;
#pragma unroll
            for (int off = 1; off < 32; off <<= 1) {
                int t = __shfl_up_sync(0xffffffffu, wsc, off);
                if (lane >= off) wsc += t;
            }
            warp_tot[lane] = wsc - wv;   // exclusive
        }
        __syncthreads();
        int excl = s_carry + warp_tot[wid] + (sc - s);
        int a0 = excl, a1 = a0 + v.x, a2 = a1 + v.y, a3 = a2 + v.z;
        if (i0 + 0 < n) { g_start[i0 + 0] = a0; g_cursor[i0 + 0] = a0; }
        if (i0 + 1 < n) { g_start[i0 + 1] = a1; g_cursor[i0 + 1] = a1; }
        if (i0 + 2 < n) { g_start[i0 + 2] = a2; g_cursor[i0 + 2] = a2; }
        if (i0 + 3 < n) { g_start[i0 + 3] = a3; g_cursor[i0 + 3] = a3; }
        __syncthreads();
        if (tid == 1023) s_carry = excl + s;
        __syncthreads();
    }
    if (tid == 0) g_start[n] = s_carry;
}

// Scatter edges into CSR order + fused leaky-relu logit (no max pass:
// logits are bounded |e| <= ~26, exp() safe in fp32).
__global__ void k_scatter(const void* ei, int E, int n) {
    int i = blockIdx.x * blockDim.x + threadIdx.x;
    if (i >= E + n) return;
    int s, d;
    if (i >= E) { s = d = i - E; }
    else if (g_is64) {
        const long long* p = (const long long*)ei;
        s = (int)p[i]; d = (int)p[i + E];
    } else {
        const int* p = (const int*)ei;
        s = p[i]; d = p[i + E];
    }
    float e = g_asrc[s] + g_adst[d];
    e = (e > 0.0f) ? e : NEG_SLOPE * e;
    int pos = atomicAdd(&g_cursor[d], 1);
    g_csr_src[pos] = s;
    g_ev[pos] = e;
}

// Fused GAT gather: softmax (no max shift) + weighted aggregate + bias + ELU.
// One warp per dst node. Masked unroll-8: all 8 row-loads issue every batch
// (clamped index, alpha=0 when OOB) -> MLP=8, no serial tail.
// csr_src/ev fetched lane-parallel (1 LDG each) + shfl broadcast.
__global__ __launch_bounds__(256) void k_gat(float* __restrict__ out,
                                             const float* __restrict__ bias,
                                             int n) {
    int gtid = blockIdx.x * blockDim.x + threadIdx.x;
    int w = gtid >> 5, lane = gtid & 31;
    if (w >= n) return;
    const int s0 = g_start[w], s1 = g_start[w + 1];

    float4 acc = make_float4(0.f, 0.f, 0.f, 0.f);
    float denom = 0.f;
    const __half* xh = g_xw_h;

    for (int j = s0; j < s1; j += 8) {
        // lane-parallel fetch of up to 8 (src, ev) pairs; lanes repeat mod 8
        int jj = j + (lane & 7); if (jj >= s1) jj = s1 - 1;
        int   sv = g_csr_src[jj];
        float ef = g_ev[jj];
#pragma unroll
        for (int t = 0; t < 8; t++) {
            int   src = __shfl_sync(0xffffffffu, sv, t);
            float e   = __shfl_sync(0xffffffffu, ef, t);
            float a   = (j + t < s1) ? __expf(e) : 0.0f;
            uint2 u = __ldg(((const uint2*)(xh + (size_t)src * DOUT)) + lane);
            denom += a;
            float2 f;
            f = __half22float2(*(__half2*)&u.x); acc.x += a * f.x; acc.y += a * f.y;
            f = __half22float2(*(__half2*)&u.y); acc.z += a * f.x; acc.w += a * f.y;
        }
    }

    float r = 1.0f / denom;
    float4 b = ((const float4*)bias)[lane];
    float4 o;
    o.x = acc.x * r + b.x; o.y = acc.y * r + b.y;
    o.z = acc.z * r + b.z; o.w = acc.w * r + b.w;
    o.x = (o.x > 0.f) ? o.x : expm1f(o.x);
    o.y = (o.y > 0.f) ? o.y : expm1f(o.y);
    o.z = (o.z > 0.f) ? o.z : expm1f(o.z);
    o.w = (o.w > 0.f) ? o.w : expm1f(o.w);
    ((float4*)(out + (size_t)w * DOUT))[lane] = o;
}

// ---------------- launch ----------------
extern "C" void kernel_launch(void* const* d_in, const int* in_sizes, int n_in,
                              void* d_out, int out_size) {
    const float* x       = (const float*)d_in[0];
    const void*  ei      = d_in[1];
    const float* W       = (const float*)d_in[2];
    const float* att_src = (const float*)d_in[3];
    const float* att_dst = (const float*)d_in[4];
    const float* bias    = (const float*)d_in[5];
    float* out = (float*)d_out;

    const int n  = in_sizes[0] / DIN;
    const int E  = in_sizes[1] / 2;
    const int EN = E + n;

    k_zero<<<(n + 255) / 256, 256>>>((const long long*)ei, n);
    k_hist<<<(EN + 255) / 256, 256>>>(ei, E, n);
    k_gemm<<<(n + 63) / 64, 256>>>(x, W, att_src, att_dst, n);
    k_scan<<<1, 1024>>>(n);
    k_scatter<<<(EN + 255) / 256, 256>>>(ei, E, n);
    k_gat<<<(n * 32 + 255) / 256, 256>>>(out, bias, n);
}

// round 10
// speedup vs baseline: 1.3685x; 1.3685x over previous
#include <cuda_runtime.h>
#include <cuda_fp16.h>
#include <cstdint>

#define DIN 128
#define DOUT 128
#define NEG_SLOPE 0.2f
#define MAX_N 50048
#define MAX_EN 860000   // E + N with slack

// ---------------- scratch (no allocations allowed) ----------------
__device__ __half   g_xw_h[(size_t)MAX_N * DOUT]; // x @ W (fp16, for gather)
__device__ float    g_asrc[MAX_N];
__device__ float    g_adst[MAX_N];
__device__ int      g_deg[MAX_N];                 // in-degree histogram
__device__ int      g_start[MAX_N];               // CSR segment start (by dst)
__device__ int      g_cursor[MAX_N];              // scatter cursors
__device__ int      g_csr_src[MAX_EN];            // src node per CSR slot
__device__ float    g_ev[MAX_EN];                 // leaky-relu logit per CSR slot
__device__ int      g_total;                      // allocator cursor
__device__ int      g_is64;

// ---------------- kernels ----------------

// Zero histogram + allocator + detect int64 vs int32 edge_index.
__global__ void k_zero(const long long* ei, int n) {
    int i = blockIdx.x * blockDim.x + threadIdx.x;
    if (i < n) g_deg[i] = 0;
    if (i == 0) {
        g_total = 0;
        bool ok = true;
#pragma unroll
        for (int t = 0; t < 8; t++) {
            long long v = ei[t];
            if (v < 0 || v >= (long long)n) ok = false;
        }
        g_is64 = ok ? 1 : 0;
    }
}

// Histogram of destinations (incl. self loops appended at the end).
__global__ void k_hist(const void* ei, int E, int n) {
    int i = blockIdx.x * blockDim.x + threadIdx.x;
    if (i >= E + n) return;
    int d;
    if (i >= E) d = i - E;
    else if (g_is64) d = (int)((const long long*)ei)[i + E];
    else             d = ((const int*)ei)[i + E];
    atomicAdd(&g_deg[d], 1);
}

// ---------------- GEMM (measured ~88% of fp32 SIMT roofline) -----------------
// xw = x @ W. 64 rows x 128 cols per block, 256 threads, BK=32.
// Fused epilogue: attention row-dots (warp shfl reduce) + fp16 store of xw.
__global__ __launch_bounds__(256) void k_gemm(const float* __restrict__ x,
                                              const float* __restrict__ W,
                                              const float* __restrict__ att_src,
                                              const float* __restrict__ att_dst,
                                              int n) {
    __shared__ float As[64][32];
    __shared__ float Bs[32][128];
    const int tid = threadIdx.x;
    const int block_row = blockIdx.x * 64;
    const int ty = tid >> 5, tx = tid & 31;
    float acc[8][4] = {};

    for (int k0 = 0; k0 < DIN; k0 += 32) {
#pragma unroll
        for (int t = tid; t < 512; t += 256) {           // A: 64x32 = 512 float4
            int r = t >> 3, kq = t & 7;
            int row = block_row + r; if (row >= n) row = n - 1;
            *(float4*)&As[r][kq * 4] =
                *(const float4*)(x + (size_t)row * DIN + k0 + kq * 4);
        }
#pragma unroll
        for (int t = tid; t < 1024; t += 256) {          // B: 32x128 = 1024 float4
            int k = t >> 5, cq = t & 31;
            *(float4*)&Bs[k][cq * 4] =
                *(const float4*)(W + (size_t)(k0 + k) * DOUT + cq * 4);
        }
        __syncthreads();
#pragma unroll
        for (int k = 0; k < 32; k++) {
            float4 b = *(float4*)&Bs[k][tx * 4];
#pragma unroll
            for (int r = 0; r < 8; r++) {
                float a = As[ty * 8 + r][k];
                acc[r][0] += a * b.x;
                acc[r][1] += a * b.y;
                acc[r][2] += a * b.z;
                acc[r][3] += a * b.w;
            }
        }
        __syncthreads();
    }

    // fused epilogue: fp16 store + attention dots
    float4 sv = ((const float4*)att_src)[tx];
    float4 dv = ((const float4*)att_dst)[tx];
#pragma unroll
    for (int r = 0; r < 8; r++) {
        int row = block_row + ty * 8 + r;
        float ps = acc[r][0] * sv.x + acc[r][1] * sv.y + acc[r][2] * sv.z + acc[r][3] * sv.w;
        float pd = acc[r][0] * dv.x + acc[r][1] * dv.y + acc[r][2] * dv.z + acc[r][3] * dv.w;
#pragma unroll
        for (int o = 16; o; o >>= 1) {
            ps += __shfl_xor_sync(0xffffffffu, ps, o);
            pd += __shfl_xor_sync(0xffffffffu, pd, o);
        }
        if (row < n) {
            __half2 h0 = __floats2half2_rn(acc[r][0], acc[r][1]);
            __half2 h1 = __floats2half2_rn(acc[r][2], acc[r][3]);
            uint2 u; u.x = *(unsigned*)&h0; u.y = *(unsigned*)&h1;
            *(uint2*)(g_xw_h + (size_t)row * DOUT + tx * 4) = u;
            if (tx == 0) { g_asrc[row] = ps; g_adst[row] = pd; }
        }
    }
}

// One-pass segment allocation: warp prefix-scan of degrees + one atomicAdd
// per warp. Segment order across nodes is arbitrary but contiguous/disjoint,
// which is all the CSR consumers need (end = start + deg).
__global__ void k_alloc(int n) {
    int i = blockIdx.x * blockDim.x + threadIdx.x;
    int lane = threadIdx.x & 31;
    int d = (i < n) ? g_deg[i] : 0;
    int sc = d;
#pragma unroll
    for (int off = 1; off < 32; off <<= 1) {
        int t = __shfl_up_sync(0xffffffffu, sc, off);
        if (lane >= off) sc += t;
    }
    int base = 0;
    if (lane == 31) base = atomicAdd(&g_total, sc);
    base = __shfl_sync(0xffffffffu, base, 31);
    if (i < n) {
        int st = base + sc - d;
        g_start[i] = st;
        g_cursor[i] = st;
    }
}

// Scatter edges into CSR order + fused leaky-relu logit (no max pass:
// logits are bounded |e| <= ~26, exp() safe in fp32).
__global__ void k_scatter(const void* ei, int E, int n) {
    int i = blockIdx.x * blockDim.x + threadIdx.x;
    if (i >= E + n) return;
    int s, d;
    if (i >= E) { s = d = i - E; }
    else if (g_is64) {
        const long long* p = (const long long*)ei;
        s = (int)p[i]; d = (int)p[i + E];
    } else {
        const int* p = (const int*)ei;
        s = p[i]; d = p[i + E];
    }
    float e = g_asrc[s] + g_adst[d];
    e = (e > 0.0f) ? e : NEG_SLOPE * e;
    int pos = atomicAdd(&g_cursor[d], 1);
    g_csr_src[pos] = s;
    g_ev[pos] = e;
}

// Fused GAT gather: softmax (no max shift) + weighted aggregate + bias + ELU.
// One warp per dst node; unroll-4 batches with exact tail (R8's measured-best).
__global__ __launch_bounds__(256) void k_gat(float* __restrict__ out,
                                             const float* __restrict__ bias,
                                             int n) {
    int gtid = blockIdx.x * blockDim.x + threadIdx.x;
    int w = gtid >> 5, lane = gtid & 31;
    if (w >= n) return;
    const int s0 = g_start[w];
    const int s1 = s0 + g_deg[w];

    float4 acc = make_float4(0.f, 0.f, 0.f, 0.f);
    float denom = 0.f;
    const __half* xh = g_xw_h;
    int j = s0;
    for (; j + 4 <= s1; j += 4) {
        int  i0 = g_csr_src[j],     i1 = g_csr_src[j + 1];
        int  i2 = g_csr_src[j + 2], i3 = g_csr_src[j + 3];
        float e0 = g_ev[j],     e1 = g_ev[j + 1];
        float e2 = g_ev[j + 2], e3 = g_ev[j + 3];
        uint2 u0 = __ldg(((const uint2*)(xh + (size_t)i0 * DOUT)) + lane);
        uint2 u1 = __ldg(((const uint2*)(xh + (size_t)i1 * DOUT)) + lane);
        uint2 u2 = __ldg(((const uint2*)(xh + (size_t)i2 * DOUT)) + lane);
        uint2 u3 = __ldg(((const uint2*)(xh + (size_t)i3 * DOUT)) + lane);
        float a0 = __expf(e0), a1 = __expf(e1);
        float a2 = __expf(e2), a3 = __expf(e3);
        denom += (a0 + a1) + (a2 + a3);
        float2 f;
        f = __half22float2(*(__half2*)&u0.x); acc.x += a0 * f.x; acc.y += a0 * f.y;
        f = __half22float2(*(__half2*)&u0.y); acc.z += a0 * f.x; acc.w += a0 * f.y;
        f = __half22float2(*(__half2*)&u1.x); acc.x += a1 * f.x; acc.y += a1 * f.y;
        f = __half22float2(*(__half2*)&u1.y); acc.z += a1 * f.x; acc.w += a1 * f.y;
        f = __half22float2(*(__half2*)&u2.x); acc.x += a2 * f.x; acc.y += a2 * f.y;
        f = __half22float2(*(__half2*)&u2.y); acc.z += a2 * f.x; acc.w += a2 * f.y;
        f = __half22float2(*(__half2*)&u3.x); acc.x += a3 * f.x; acc.y += a3 * f.y;
        f = __half22float2(*(__half2*)&u3.y); acc.z += a3 * f.x; acc.w += a3 * f.y;
    }
    for (; j < s1; j++) {
        int   i0 = g_csr_src[j];
        float a0 = __expf(g_ev[j]);
        uint2 u0 = __ldg(((const uint2*)(xh + (size_t)i0 * DOUT)) + lane);
        denom += a0;
        float2 f;
        f = __half22float2(*(__half2*)&u0.x); acc.x += a0 * f.x; acc.y += a0 * f.y;
        f = __half22float2(*(__half2*)&u0.y); acc.z += a0 * f.x; acc.w += a0 * f.y;
    }

    float r = 1.0f / denom;
    float4 b = ((const float4*)bias)[lane];
    float4 o;
    o.x = acc.x * r + b.x; o.y = acc.y * r + b.y;
    o.z = acc.z * r + b.z; o.w = acc.w * r + b.w;
    o.x = (o.x > 0.f) ? o.x : expm1f(o.x);
    o.y = (o.y > 0.f) ? o.y : expm1f(o.y);
    o.z = (o.z > 0.f) ? o.z : expm1f(o.z);
    o.w = (o.w > 0.f) ? o.w : expm1f(o.w);
    ((float4*)(out + (size_t)w * DOUT))[lane] = o;
}

// ---------------- launch ----------------
extern "C" void kernel_launch(void* const* d_in, const int* in_sizes, int n_in,
                              void* d_out, int out_size) {
    const float* x       = (const float*)d_in[0];
    const void*  ei      = d_in[1];
    const float* W       = (const float*)d_in[2];
    const float* att_src = (const float*)d_in[3];
    const float* att_dst = (const float*)d_in[4];
    const float* bias    = (const float*)d_in[5];
    float* out = (float*)d_out;

    const int n  = in_sizes[0] / DIN;
    const int E  = in_sizes[1] / 2;
    const int EN = E + n;

    k_zero<<<(n + 255) / 256, 256>>>((const long long*)ei, n);
    k_hist<<<(EN + 255) / 256, 256>>>(ei, E, n);
    k_gemm<<<(n + 63) / 64, 256>>>(x, W, att_src, att_dst, n);
    k_alloc<<<(n + 255) / 256, 256>>>(n);
    k_scatter<<<(EN + 255) / 256, 256>>>(ei, E, n);
    k_gat<<<(n * 32 + 255) / 256, 256>>>(out, bias, n);
}